// round 15
// baseline (speedup 1.0000x reference)
#include <cuda_runtime.h>
#include <cuda_bf16.h>

// CapsuleRoutingPooling — FINAL (committed; search exhausted; held).
//
// Analytic collapse: the reference's routing softmax is over axis=3, which
// has size 1, so c == 1 identically and the 3-iteration dynamic-routing
// loop has no effect on the output. The whole op reduces to
//   out = squash( 2x2 spatial sum-pool of the D=16 capsule vectors ).
//
// Shapes: B=16, C=64, H=W=64, D=16, k=2 -> nH=nW=32,
// output vectors = 16*64*32*32 = 1,048,576.
//
// Best-measured configuration (bench 52.86us best; 52.9-53.3us band over
// 9 validation runs; DRAM ~80%, ~6.6 TB/s = ~82.7% of 8 TB/s spec):
// 4 threads per output vector, one float4 each; plain cached loads;
// __stcs streaming stores; oversubscribed grid 16384 x 256.
// Traffic (256 MB read + 64 MB write) is the mandatory minimum.
// Full sweep, all neutral-or-worse: ILP/MLP 8, __ldcs loads, .wt stores,
// dense 512B/warp request shaping, persistent grid (-15%), block 128/512.
// HBM-ceiling-bound; no remaining mechanism.

static constexpr int NVEC = 16 * 64 * 32 * 32;     // output vectors
static constexpr int NTHREADS_TOTAL = NVEC * 4;    // 4,194,304

__global__ void __launch_bounds__(256)
capsule_pool_squash_kernel(const float* __restrict__ inp, float* __restrict__ out) {
    int gid  = blockIdx.x * blockDim.x + threadIdx.x;
    int v    = gid >> 2;      // output vector id
    int lane = gid & 3;       // which float4 of the D=16 vector

    // v = ((bc)*32 + nh)*32 + nw
    int bc = v >> 10;         // b*C + c   (0..1023)
    int t  = v & 1023;
    int nh = t >> 5;
    int nw = t & 31;

    // input float4 indexing: row (b,c,h) has W*D/4 = 256 float4s; w step = D/4 = 4
    const float4* __restrict__ in4 = (const float4*)inp;
    int base4 = (bc * 64 + (nh << 1)) * 256 + (nw << 3) + lane;

    float4 p00 = in4[base4];
    float4 p01 = in4[base4 + 4];
    float4 p10 = in4[base4 + 256];
    float4 p11 = in4[base4 + 260];

    float4 s;
    s.x = (p00.x + p01.x) + (p10.x + p11.x);
    s.y = (p00.y + p01.y) + (p10.y + p11.y);
    s.z = (p00.z + p01.z) + (p10.z + p11.z);
    s.w = (p00.w + p01.w) + (p10.w + p11.w);

    // squared norm over D=16: reduce across the 4 lanes of this vector
    float sq = s.x * s.x + s.y * s.y + s.z * s.z + s.w * s.w;
    sq += __shfl_xor_sync(0xffffffffu, sq, 1);
    sq += __shfl_xor_sync(0xffffffffu, sq, 2);

    // squash scale: sq/(1+sq) * 1/(sqrt(sq)+1e-8)
    float scale = sq / ((1.0f + sq) * (sqrtf(sq) + 1e-8f));

    float4 o;
    o.x = s.x * scale;
    o.y = s.y * scale;
    o.z = s.z * scale;
    o.w = s.w * scale;

    __stcs(&((float4*)out)[(v << 2) + lane], o);
}

extern "C" void kernel_launch(void* const* d_in, const int* in_sizes, int n_in,
                              void* d_out, int out_size) {
    const float* inp = (const float*)d_in[0];
    float* out = (float*)d_out;
    int threads = 256;
    int blocks = NTHREADS_TOTAL / threads;   // 16384
    capsule_pool_squash_kernel<<<blocks, threads>>>(inp, out);
}

// round 16
// speedup vs baseline: 1.0048x; 1.0048x over previous
#include <cuda_runtime.h>
#include <cuda_bf16.h>

// CapsuleRoutingPooling — FINAL (committed; search exhausted; held).
//
// Analytic collapse: the reference's routing softmax is over axis=3, which
// has size 1, so c == 1 identically and the 3-iteration dynamic-routing
// loop has no effect on the output. The whole op reduces to
//   out = squash( 2x2 spatial sum-pool of the D=16 capsule vectors ).
//
// Shapes: B=16, C=64, H=W=64, D=16, k=2 -> nH=nW=32,
// output vectors = 16*64*32*32 = 1,048,576.
//
// Best-measured configuration (bench 52.86us best; 52.9-53.3us band over
// 10 validation runs; DRAM ~80%, ~6.6 TB/s = ~82.7% of 8 TB/s spec):
// 4 threads per output vector, one float4 each; plain cached loads;
// __stcs streaming stores; oversubscribed grid 16384 x 256.
// Traffic (256 MB read + 64 MB write) is the mandatory minimum.
// Full sweep, all neutral-or-worse: ILP/MLP 8, __ldcs loads, .wt stores,
// dense 512B/warp request shaping, persistent grid (-15%), block 128/512.
// HBM-ceiling-bound; no remaining mechanism.

static constexpr int NVEC = 16 * 64 * 32 * 32;     // output vectors
static constexpr int NTHREADS_TOTAL = NVEC * 4;    // 4,194,304

__global__ void __launch_bounds__(256)
capsule_pool_squash_kernel(const float* __restrict__ inp, float* __restrict__ out) {
    int gid  = blockIdx.x * blockDim.x + threadIdx.x;
    int v    = gid >> 2;      // output vector id
    int lane = gid & 3;       // which float4 of the D=16 vector

    // v = ((bc)*32 + nh)*32 + nw
    int bc = v >> 10;         // b*C + c   (0..1023)
    int t  = v & 1023;
    int nh = t >> 5;
    int nw = t & 31;

    // input float4 indexing: row (b,c,h) has W*D/4 = 256 float4s; w step = D/4 = 4
    const float4* __restrict__ in4 = (const float4*)inp;
    int base4 = (bc * 64 + (nh << 1)) * 256 + (nw << 3) + lane;

    float4 p00 = in4[base4];
    float4 p01 = in4[base4 + 4];
    float4 p10 = in4[base4 + 256];
    float4 p11 = in4[base4 + 260];

    float4 s;
    s.x = (p00.x + p01.x) + (p10.x + p11.x);
    s.y = (p00.y + p01.y) + (p10.y + p11.y);
    s.z = (p00.z + p01.z) + (p10.z + p11.z);
    s.w = (p00.w + p01.w) + (p10.w + p11.w);

    // squared norm over D=16: reduce across the 4 lanes of this vector
    float sq = s.x * s.x + s.y * s.y + s.z * s.z + s.w * s.w;
    sq += __shfl_xor_sync(0xffffffffu, sq, 1);
    sq += __shfl_xor_sync(0xffffffffu, sq, 2);

    // squash scale: sq/(1+sq) * 1/(sqrt(sq)+1e-8)
    float scale = sq / ((1.0f + sq) * (sqrtf(sq) + 1e-8f));

    float4 o;
    o.x = s.x * scale;
    o.y = s.y * scale;
    o.z = s.z * scale;
    o.w = s.w * scale;

    __stcs(&((float4*)out)[(v << 2) + lane], o);
}

extern "C" void kernel_launch(void* const* d_in, const int* in_sizes, int n_in,
                              void* d_out, int out_size) {
    const float* inp = (const float*)d_in[0];
    float* out = (float*)d_out;
    int threads = 256;
    int blocks = NTHREADS_TOTAL / threads;   // 16384
    capsule_pool_squash_kernel<<<blocks, threads>>>(inp, out);
}